// round 8
// baseline (speedup 1.0000x reference)
#include <cuda_runtime.h>
#include <math.h>

// Problem constants (fixed by the dataset: B=16, H=W=8, CIN=COUT=32)
#define CI 32
#define CO 32
#define CH 18
#define CHV 16            // vote channels in SMEM (coords handled closed-form)
#define NB 16
#define NSPAT 64
#define NTOT 1024
#define EPSV 1e-9f
#define LN10 2.3025850929940457f

__device__ float g_act[NTOT * CO];            // act_out per (n, c)
__device__ float g_miu[NTOT * CO * CH];       // miu per (n, c, ch)

__device__ __forceinline__ float warp_sum(float v) {
#pragma unroll
    for (int o = 16; o; o >>= 1) v += __shfl_xor_sync(0xffffffffu, v, o);
    return v;
}
__device__ __forceinline__ float warp_max(float v) {
#pragma unroll
    for (int o = 16; o; o >>= 1) v = fmaxf(v, __shfl_xor_sync(0xffffffffu, v, o));
    return v;
}

// 75 KB. Lifetime unions: xs (pre-vote) aliases rs (post-it0);
// pa (read up to it2-E) aliases cost (written it2-M, read at the end).
struct SM {
    float  vs[CHV][CI * CO];     // votes [ch-2][i*32+c]          (64 KB)
    union {
        float xs[CI * 17];       // raw x row, dead after votes
        float rs[CI * CO];       // c-normalized routing [i*32+c]
    } u;
    union {
        float pa[CH][CO];        // lp = pa + v*(pb + pg*v); dead after it2-E
        float cost[CH][CO];      // written it2-M, read by final softmax
    } q;
    float2 pbg[CH][CO];          // (pb, pg)
    float  logit[CO];
};

// M-step, one-pass moments, balanced: warp w owns vote channel
// (w<2 ? w+16 : w); warps 0,1 additionally own coord channel w, fused into
// the SAME i-loop (coord needs only T0, already being accumulated).
// All warps: exactly 64 LDS on the critical path.
template<bool UNIFORM, bool LAST>
__device__ __forceinline__ void m_step(SM* sm, int c, int wid, float cx, float cy,
                                       int n, const float* __restrict__ beta_v)
{
    const int chv = (wid < 2) ? wid + 16 : wid;
    const float* vcol = &sm->vs[chv - 2][c];
    const float* rcol = &sm->u.rs[c];

    float T0 = 0.0f, T1 = 0.0f, T2 = 0.0f;
    if (UNIFORM) {
#pragma unroll
        for (int i = 0; i < CI; i++) {
            const float vv = vcol[i * 32];
            T1 += vv;
            T2 = fmaf(vv, vv, T2);
        }
        T0 = 1.0f;
    } else {
#pragma unroll
        for (int i = 0; i < CI; i++) {
            const float rv = rcol[i * 32];
            const float vv = vcol[i * 32];
            T0 += rv;
            T1 = fmaf(rv, vv, T1);
            T2 = fmaf(rv * vv, vv, T2);
        }
    }

    // vote channel chv
    {
        float mu_, sig;
        if (UNIFORM) {
            mu_ = T1 * 0.03125f;
            sig = fmaxf(fmaf(-mu_, mu_, T2 * 0.03125f), 0.0f) + EPSV;
        } else {
            const float inv = __fdividef(1.0f, T0 + EPSV);
            mu_ = T1 * inv;
            sig = fmaxf(fmaf(-mu_, mu_, T2 * inv), 0.0f) + EPSV;
        }
        const float hl   = 0.5f * __logf(sig);
        const float i2sv = __fdividef(0.5f, sig);
        if (!LAST) {
            sm->q.pa[chv][c] = -fmaf(mu_ * mu_, i2sv, hl);
            sm->pbg[chv][c]  = make_float2(2.0f * mu_ * i2sv, -i2sv);
            if (!UNIFORM && wid == 0) sm->logit[c] = T0;
        } else {
            g_miu[n * (CO * CH) + c * CH + chv] = mu_;
            sm->q.cost[chv][c] = (beta_v[c * CH + chv] + hl) * T0;
        }
    }

    // coord channel (warps 0,1 only): vote constant over i -> closed form on T0
    if (wid < 2) {
        const float rs_ = UNIFORM ? 1.0f : T0;
        const float inv = __fdividef(1.0f, rs_ + EPSV);
        const float vv  = (wid == 0) ? cx : cy;
        const float mu_ = vv * rs_ * inv;
        const float d   = vv - mu_;
        const float sig = d * d * rs_ * inv + EPSV;
        const float hl   = 0.5f * __logf(sig);
        const float i2sv = __fdividef(0.5f, sig);
        if (!LAST) {
            sm->q.pa[wid][c] = -fmaf(mu_ * mu_, i2sv, hl);
            sm->pbg[wid][c]  = make_float2(2.0f * mu_ * i2sv, -i2sv);
        } else {
            g_miu[n * (CO * CH) + c * CH + wid] = mu_;
            sm->q.cost[wid][c] = (beta_v[c * CH + wid] + hl) * rs_;
        }
    }
}

// E-step (warp wid = i-pair {wid, wid+16}, lane = c). Votes read from SMEM —
// no persistent vote registers (frees ~32 regs for load batching).
__device__ __forceinline__ void e_step(SM* sm, int c, int wid,
                                       float cx, float cy,
                                       float act0, float act1, float ao_reg)
{
    float S0 = 0.0f, m0 = -1e30f, S1 = 0.0f, m1 = -1e30f;
#pragma unroll
    for (int ch = 0; ch < CH; ch++) {
        const float  pav = sm->q.pa[ch][c];
        const float2 bg  = sm->pbg[ch][c];
        float vv0, vv1;
        if (ch == 0)      { vv0 = cx; vv1 = cx; }
        else if (ch == 1) { vv0 = cy; vv1 = cy; }
        else {
            vv0 = sm->vs[ch - 2][wid * 32 + c];
            vv1 = sm->vs[ch - 2][(wid + 16) * 32 + c];
        }
        const float l0 = fmaf(fmaf(bg.y, vv0, bg.x), vv0, pav);
        const float l1 = fmaf(fmaf(bg.y, vv1, bg.x), vv1, pav);
        S0 += l0; m0 = fmaxf(m0, l0);
        S1 += l1; m1 = fmaxf(m1, l1);
    }
    const float M0 = warp_max(m0);
    const float M1 = warp_max(m1);
    const float pv0 = __expf(S0 - 18.0f * M0 + 18.0f * LN10);
    const float pv1 = __expf(S1 - 18.0f * M1 + 18.0f * LN10);
    const float ap0 = pv0 * ao_reg;
    const float ap1 = pv1 * ao_reg;
    const float sa0 = warp_sum(ap0);
    const float sa1 = warp_sum(ap1);
    // Σ_c(ap/(sa+EPS)·act) = act·sa/(sa+EPS): act const over c -> no shuffle
    const float rv0 = (ap0 / (sa0 + EPSV)) * act0;
    const float rv1 = (ap1 / (sa1 + EPSV)) * act1;
    const float t0  = act0 * (sa0 / (sa0 + EPSV));
    const float t1  = act1 * (sa1 / (sa1 + EPSV));
    sm->u.rs[wid * 32 + c]        = rv0 / (t0 + EPSV);
    sm->u.rs[(wid + 16) * 32 + c] = rv1 / (t1 + EPSV);
}

// One CTA per spatial position n. 512 threads, 16 warps. 7 barriers total.
__global__ void __launch_bounds__(512, 2)
caps_kernel(const float* __restrict__ x,
            const float* __restrict__ w,
            const float* __restrict__ beta_v,
            const float* __restrict__ beta_a,
            const float* __restrict__ coord)
{
    extern __shared__ float smem_raw[];
    SM* sm = reinterpret_cast<SM*>(smem_raw);

    const int tid = threadIdx.x;
    const int c   = tid & 31;
    const int wid = tid >> 5;
    const int n   = blockIdx.x;

    for (int k = tid; k < CI * 17; k += 512) sm->u.xs[k] = x[n * (CI * 17) + k];
    __syncthreads();                                         // B1

    // --- votes: pose_i (4x4) @ w[i][c] (4x4) for i = wid, wid+16; stored to SMEM ---
#pragma unroll
    for (int s = 0; s < 2; s++) {
        const int i = wid + 16 * s;
        const float4* wv = reinterpret_cast<const float4*>(w) + (i * CO + c) * 4;
        const float4 w0 = wv[0], w1 = wv[1], w2 = wv[2], w3 = wv[3];
        const float* pr = &sm->u.xs[i * 17];
#pragma unroll
        for (int a = 0; a < 4; a++) {
            const float p0 = pr[a * 4 + 0], p1 = pr[a * 4 + 1];
            const float p2 = pr[a * 4 + 2], p3 = pr[a * 4 + 3];
            sm->vs[a * 4 + 0][i * 32 + c] = p0 * w0.x + p1 * w1.x + p2 * w2.x + p3 * w3.x;
            sm->vs[a * 4 + 1][i * 32 + c] = p0 * w0.y + p1 * w1.y + p2 * w2.y + p3 * w3.y;
            sm->vs[a * 4 + 2][i * 32 + c] = p0 * w0.z + p1 * w1.z + p2 * w2.z + p3 * w3.z;
            sm->vs[a * 4 + 3][i * 32 + c] = p0 * w0.w + p1 * w1.w + p2 * w2.w + p3 * w3.w;
        }
    }
    const float act0 = sm->u.xs[wid * 17 + 16];
    const float act1 = sm->u.xs[(wid + 16) * 17 + 16];
    const int sp = n & (NSPAT - 1);
    const float cx = coord[2 * sp], cy = coord[2 * sp + 1];
    __syncthreads();                                         // B2 (vs ready; xs dead)

    // ---- it0: uniform weights; softmax of equal logits is exactly 1/32 ----
    m_step<true, false>(sm, c, wid, cx, cy, n, beta_v);
    __syncthreads();                                         // B3

    // ---- it1: ao = 1/32 (constant, no softmax phase) ----
    e_step(sm, c, wid, cx, cy, act0, act1, 0.03125f);
    __syncthreads();                                         // B4
    m_step<false, false>(sm, c, wid, cx, cy, n, beta_v);
    __syncthreads();                                         // B5

    // ---- it2: softmax(logit) inlined per-warp (no separate phase) ----
    float ao_reg;
    {
        const float t  = sm->logit[c];
        const float mx = warp_max(t);
        const float e  = __expf(t - mx);
        const float se = warp_sum(e);
        ao_reg = e / se;
    }
    e_step(sm, c, wid, cx, cy, act0, act1, ao_reg);
    __syncthreads();                                         // B6
    m_step<false, true>(sm, c, wid, cx, cy, n, beta_v);      // writes g_miu + cost
    __syncthreads();                                         // B7

    // final activation softmax: warp 0 only; other warps exit
    if (tid < 32) {
        float cs = 0.0f;
#pragma unroll
        for (int ch = 0; ch < CH; ch++) cs += sm->q.cost[ch][c];
        const float t  = 0.03f * (beta_a[c] - cs);
        const float mx = warp_max(t);
        const float e  = __expf(t - mx);
        const float se = warp_sum(e);
        g_act[n * CO + c] = e / se;
    }
}

// Deterministic spatial mean: 8 partials of 8 sp each, fixed combine order.
__global__ void reduce_kernel(float* __restrict__ out)
{
    __shared__ float part[256];
    const int NA = NB * CO;                 // 512
    const int NP = NB * CO * CH;            // 9216
    const int jl = threadIdx.x & 31;
    const int q  = threadIdx.x >> 5;        // 0..7: 8 spatial each
    const int j  = blockIdx.x * 32 + jl;

    float s = 0.0f;
    if (j < NA + NP) {
        const float* src;
        int base, stride;
        if (j < NA) {
            const int b = j >> 5, cc = j & 31;
            src = g_act; base = b * NSPAT * CO + cc; stride = CO;
        } else {
            const int jj = j - NA;
            const int b = jj / (CO * CH), rem = jj % (CO * CH);
            src = g_miu; base = b * NSPAT * (CO * CH) + rem; stride = CO * CH;
        }
#pragma unroll
        for (int sp = q * 8; sp < q * 8 + 8; sp++) s += src[base + sp * stride];
    }
    part[threadIdx.x] = s;
    __syncthreads();
    if (threadIdx.x < 32 && j < NA + NP) {
        float t = 0.0f;
#pragma unroll
        for (int k = 0; k < 8; k++) t += part[jl + 32 * k];
        out[j] = t * (1.0f / NSPAT);
    }
}

extern "C" void kernel_launch(void* const* d_in, const int* in_sizes, int n_in,
                              void* d_out, int out_size)
{
    const float* x      = (const float*)d_in[0];
    const float* w      = (const float*)d_in[1];
    const float* beta_v = (const float*)d_in[2];
    const float* beta_a = (const float*)d_in[3];
    const float* coord  = (const float*)d_in[4];
    float* out = (float*)d_out;

    const size_t smem = sizeof(SM);        // ~75 KB -> 2 CTAs/SM
    cudaFuncSetAttribute(caps_kernel, cudaFuncAttributeMaxDynamicSharedMemorySize, (int)smem);

    caps_kernel<<<NTOT, 512, smem>>>(x, w, beta_v, beta_a, coord);

    const int total = NB * CO + NB * CO * CH;   // 9728
    reduce_kernel<<<(total + 31) / 32, 256>>>(out);
}

// round 9
// speedup vs baseline: 1.0552x; 1.0552x over previous
#include <cuda_runtime.h>
#include <math.h>

// Problem constants (fixed by the dataset: B=16, H=W=8, CIN=COUT=32)
#define CI 32
#define CO 32
#define CH 18
#define CHV 16            // vote channels in SMEM (coords handled closed-form)
#define NB 16
#define NSPAT 64
#define NTOT 1024
#define EPSV 1e-9f
#define LN10 2.3025850929940457f

__device__ float g_act[NTOT * CO];            // act_out per (n, c)
__device__ float g_miu[NTOT * CO * CH];       // miu per (n, c, ch)

__device__ __forceinline__ float warp_sum(float v) {
#pragma unroll
    for (int o = 16; o; o >>= 1) v += __shfl_xor_sync(0xffffffffu, v, o);
    return v;
}
__device__ __forceinline__ float warp_max(float v) {
#pragma unroll
    for (int o = 16; o; o >>= 1) v = fmaxf(v, __shfl_xor_sync(0xffffffffu, v, o));
    return v;
}

// 76,672 B exactly; 3 CTAs/SM: 3*(76672+1024) = 233,088 <= 233,472 (228 KB).
struct SM {
    float  vs[CHV][CI * CO];     // votes [ch-2][i*32+c]          (64 KB)
    union {
        float xs[CI * 17];       // raw x row, dead after votes
        float rs[CI * CO];       // c-normalized routing [i*32+c]
    } u;
    union {
        float pa[CH][CO];        // lp = pa + v*(pb + pg*v); dead after it2-E
        float cost[CH][CO];      // written it2-M, read by final softmax
    } q;
    float2 pbg[CH][CO];          // (pb, pg)
    float  logit[CO];
};

// M-step, one-pass moments, balanced: warp w owns vote channel
// (w<2 ? w+16 : w); warps 0,1 additionally own coord channel w, fused into
// the SAME i-loop (coord needs only T0, already being accumulated).
template<bool UNIFORM, bool LAST>
__device__ __forceinline__ void m_step(SM* sm, int c, int wid, float cx, float cy,
                                       int n, const float* __restrict__ beta_v)
{
    const int chv = (wid < 2) ? wid + 16 : wid;
    const float* vcol = &sm->vs[chv - 2][c];
    const float* rcol = &sm->u.rs[c];

    float T0 = 0.0f, T1 = 0.0f, T2 = 0.0f;
    if (UNIFORM) {
#pragma unroll
        for (int i = 0; i < CI; i++) {
            const float vv = vcol[i * 32];
            T1 += vv;
            T2 = fmaf(vv, vv, T2);
        }
        T0 = 1.0f;
    } else {
#pragma unroll
        for (int i = 0; i < CI; i++) {
            const float rv = rcol[i * 32];
            const float vv = vcol[i * 32];
            T0 += rv;
            T1 = fmaf(rv, vv, T1);
            T2 = fmaf(rv * vv, vv, T2);
        }
    }

    // vote channel chv
    {
        float mu_, sig;
        if (UNIFORM) {
            mu_ = T1 * 0.03125f;
            sig = fmaxf(fmaf(-mu_, mu_, T2 * 0.03125f), 0.0f) + EPSV;
        } else {
            const float inv = __fdividef(1.0f, T0 + EPSV);
            mu_ = T1 * inv;
            sig = fmaxf(fmaf(-mu_, mu_, T2 * inv), 0.0f) + EPSV;
        }
        const float hl   = 0.5f * __logf(sig);
        const float i2sv = __fdividef(0.5f, sig);
        if (!LAST) {
            sm->q.pa[chv][c] = -fmaf(mu_ * mu_, i2sv, hl);
            sm->pbg[chv][c]  = make_float2(2.0f * mu_ * i2sv, -i2sv);
            if (!UNIFORM && wid == 0) sm->logit[c] = T0;
        } else {
            g_miu[n * (CO * CH) + c * CH + chv] = mu_;
            sm->q.cost[chv][c] = (beta_v[c * CH + chv] + hl) * T0;
        }
    }

    // coord channel (warps 0,1 only): vote constant over i -> closed form on T0
    if (wid < 2) {
        const float rs_ = UNIFORM ? 1.0f : T0;
        const float inv = __fdividef(1.0f, rs_ + EPSV);
        const float vv  = (wid == 0) ? cx : cy;
        const float mu_ = vv * rs_ * inv;
        const float d   = vv - mu_;
        const float sig = d * d * rs_ * inv + EPSV;
        const float hl   = 0.5f * __logf(sig);
        const float i2sv = __fdividef(0.5f, sig);
        if (!LAST) {
            sm->q.pa[wid][c] = -fmaf(mu_ * mu_, i2sv, hl);
            sm->pbg[wid][c]  = make_float2(2.0f * mu_ * i2sv, -i2sv);
        } else {
            g_miu[n * (CO * CH) + c * CH + wid] = mu_;
            sm->q.cost[wid][c] = (beta_v[c * CH + wid] + hl) * rs_;
        }
    }
}

// E-step (warp wid = i-pair {wid, wid+16}, lane = c). Votes read from SMEM.
__device__ __forceinline__ void e_step(SM* sm, int c, int wid,
                                       float cx, float cy,
                                       float act0, float act1, float ao_reg)
{
    float S0 = 0.0f, m0 = -1e30f, S1 = 0.0f, m1 = -1e30f;
#pragma unroll
    for (int ch = 0; ch < CH; ch++) {
        const float  pav = sm->q.pa[ch][c];
        const float2 bg  = sm->pbg[ch][c];
        float vv0, vv1;
        if (ch == 0)      { vv0 = cx; vv1 = cx; }
        else if (ch == 1) { vv0 = cy; vv1 = cy; }
        else {
            vv0 = sm->vs[ch - 2][wid * 32 + c];
            vv1 = sm->vs[ch - 2][(wid + 16) * 32 + c];
        }
        const float l0 = fmaf(fmaf(bg.y, vv0, bg.x), vv0, pav);
        const float l1 = fmaf(fmaf(bg.y, vv1, bg.x), vv1, pav);
        S0 += l0; m0 = fmaxf(m0, l0);
        S1 += l1; m1 = fmaxf(m1, l1);
    }
    const float M0 = warp_max(m0);
    const float M1 = warp_max(m1);
    const float pv0 = __expf(S0 - 18.0f * M0 + 18.0f * LN10);
    const float pv1 = __expf(S1 - 18.0f * M1 + 18.0f * LN10);
    const float ap0 = pv0 * ao_reg;
    const float ap1 = pv1 * ao_reg;
    const float sa0 = warp_sum(ap0);
    const float sa1 = warp_sum(ap1);
    // Σ_c(ap/(sa+EPS)·act) = act·sa/(sa+EPS): act const over c -> no shuffle
    const float rv0 = (ap0 / (sa0 + EPSV)) * act0;
    const float rv1 = (ap1 / (sa1 + EPSV)) * act1;
    const float t0  = act0 * (sa0 / (sa0 + EPSV));
    const float t1  = act1 * (sa1 / (sa1 + EPSV));
    sm->u.rs[wid * 32 + c]        = rv0 / (t0 + EPSV);
    sm->u.rs[(wid + 16) * 32 + c] = rv1 / (t1 + EPSV);
}

// One CTA per spatial position n. 512 threads, 16 warps, 3 CTAs/SM target.
__global__ void __launch_bounds__(512, 3)
caps_kernel(const float* __restrict__ x,
            const float* __restrict__ w,
            const float* __restrict__ beta_v,
            const float* __restrict__ beta_a,
            const float* __restrict__ coord)
{
    extern __shared__ float smem_raw[];
    SM* sm = reinterpret_cast<SM*>(smem_raw);

    const int tid = threadIdx.x;
    const int c   = tid & 31;
    const int wid = tid >> 5;
    const int n   = blockIdx.x;

    for (int k = tid; k < CI * 17; k += 512) sm->u.xs[k] = x[n * (CI * 17) + k];
    __syncthreads();                                         // B1

    // --- votes: pose_i (4x4) @ w[i][c] (4x4) for i = wid, wid+16 -> SMEM ---
#pragma unroll
    for (int s = 0; s < 2; s++) {
        const int i = wid + 16 * s;
        const float4* wv = reinterpret_cast<const float4*>(w) + (i * CO + c) * 4;
        const float4 w0 = wv[0], w1 = wv[1], w2 = wv[2], w3 = wv[3];
        const float* pr = &sm->u.xs[i * 17];
#pragma unroll
        for (int a = 0; a < 4; a++) {
            const float p0 = pr[a * 4 + 0], p1 = pr[a * 4 + 1];
            const float p2 = pr[a * 4 + 2], p3 = pr[a * 4 + 3];
            sm->vs[a * 4 + 0][i * 32 + c] = p0 * w0.x + p1 * w1.x + p2 * w2.x + p3 * w3.x;
            sm->vs[a * 4 + 1][i * 32 + c] = p0 * w0.y + p1 * w1.y + p2 * w2.y + p3 * w3.y;
            sm->vs[a * 4 + 2][i * 32 + c] = p0 * w0.z + p1 * w1.z + p2 * w2.z + p3 * w3.z;
            sm->vs[a * 4 + 3][i * 32 + c] = p0 * w0.w + p1 * w1.w + p2 * w2.w + p3 * w3.w;
        }
    }
    const float act0 = sm->u.xs[wid * 17 + 16];
    const float act1 = sm->u.xs[(wid + 16) * 17 + 16];
    const int sp = n & (NSPAT - 1);
    const float cx = coord[2 * sp], cy = coord[2 * sp + 1];
    __syncthreads();                                         // B2 (vs ready; xs dead)

    // ---- it0: uniform weights; softmax of equal logits is exactly 1/32 ----
    m_step<true, false>(sm, c, wid, cx, cy, n, beta_v);
    __syncthreads();                                         // B3

    // ---- it1: ao = 1/32 (constant, no softmax phase) ----
    e_step(sm, c, wid, cx, cy, act0, act1, 0.03125f);
    __syncthreads();                                         // B4
    m_step<false, false>(sm, c, wid, cx, cy, n, beta_v);
    __syncthreads();                                         // B5

    // ---- it2: softmax(logit) inlined per-warp (no separate phase) ----
    float ao_reg;
    {
        const float t  = sm->logit[c];
        const float mx = warp_max(t);
        const float e  = __expf(t - mx);
        const float se = warp_sum(e);
        ao_reg = e / se;
    }
    e_step(sm, c, wid, cx, cy, act0, act1, ao_reg);
    __syncthreads();                                         // B6
    m_step<false, true>(sm, c, wid, cx, cy, n, beta_v);      // writes g_miu + cost
    __syncthreads();                                         // B7

    // final activation softmax: warp 0 only; other warps exit
    if (tid < 32) {
        float cs = 0.0f;
#pragma unroll
        for (int ch = 0; ch < CH; ch++) cs += sm->q.cost[ch][c];
        const float t  = 0.03f * (beta_a[c] - cs);
        const float mx = warp_max(t);
        const float e  = __expf(t - mx);
        const float se = warp_sum(e);
        g_act[n * CO + c] = e / se;
    }
}

// Deterministic spatial mean: 8 partials of 8 sp each, fixed combine order.
__global__ void reduce_kernel(float* __restrict__ out)
{
    __shared__ float part[256];
    const int NA = NB * CO;                 // 512
    const int NP = NB * CO * CH;            // 9216
    const int jl = threadIdx.x & 31;
    const int q  = threadIdx.x >> 5;        // 0..7: 8 spatial each
    const int j  = blockIdx.x * 32 + jl;

    float s = 0.0f;
    if (j < NA + NP) {
        const float* src;
        int base, stride;
        if (j < NA) {
            const int b = j >> 5, cc = j & 31;
            src = g_act; base = b * NSPAT * CO + cc; stride = CO;
        } else {
            const int jj = j - NA;
            const int b = jj / (CO * CH), rem = jj % (CO * CH);
            src = g_miu; base = b * NSPAT * (CO * CH) + rem; stride = CO * CH;
        }
#pragma unroll
        for (int sp = q * 8; sp < q * 8 + 8; sp++) s += src[base + sp * stride];
    }
    part[threadIdx.x] = s;
    __syncthreads();
    if (threadIdx.x < 32 && j < NA + NP) {
        float t = 0.0f;
#pragma unroll
        for (int k = 0; k < 8; k++) t += part[jl + 32 * k];
        out[j] = t * (1.0f / NSPAT);
    }
}

extern "C" void kernel_launch(void* const* d_in, const int* in_sizes, int n_in,
                              void* d_out, int out_size)
{
    const float* x      = (const float*)d_in[0];
    const float* w      = (const float*)d_in[1];
    const float* beta_v = (const float*)d_in[2];
    const float* beta_a = (const float*)d_in[3];
    const float* coord  = (const float*)d_in[4];
    float* out = (float*)d_out;

    const size_t smem = sizeof(SM);        // 76,672 B -> 3 CTAs/SM
    cudaFuncSetAttribute(caps_kernel, cudaFuncAttributeMaxDynamicSharedMemorySize, (int)smem);

    caps_kernel<<<NTOT, 512, smem>>>(x, w, beta_v, beta_a, coord);

    const int total = NB * CO + NB * CO * CH;   // 9728
    reduce_kernel<<<(total + 31) / 32, 256>>>(out);
}